// round 4
// baseline (speedup 1.0000x reference)
#include <cuda_runtime.h>
#include <cuda_bf16.h>
#include <cstdint>

// Problem dims
#define Bsz   128
#define Tsz   512
#define INsz  128
#define Hsz   1024
#define G3sz  3072
#define PREDsz 96
#define MR    (Tsz*Bsz)        // 65536 rows
#define BH    (Bsz*Hsz)        // 131072

// Scan kernel config: 128 persistent CTAs, 8 hidden units each
#define NCTA  128
#define UPC   8                // units per CTA
#define GR    (3*UPC)          // gate rows per CTA = 24
#define WS    1028             // smem weight row stride (floats), conflict-free
#define GS    26               // smem gate buffer row stride (floats)
#define SCAN_SMEM_FLOATS (GR*WS + 32 + Bsz*GS)
#define SCAN_SMEM_BYTES  (SCAN_SMEM_FLOATS*4)   // ~112 KB

// ---------------- device scratch (allocation-free rule) ----------------
__device__ float g_xi [(size_t)MR*G3sz];   // [T,B,3H] input-side gate projections
__device__ float g_hsA[(size_t)MR*Hsz];    // [T,B,H] hidden sequence buffer A
__device__ float g_hsB[(size_t)MR*Hsz];    // [T,B,H] hidden sequence buffer B
__device__ unsigned g_bar_cnt = 0;
__device__ unsigned g_bar_gen = 0;

// ---------------- helpers ----------------
__device__ __forceinline__ unsigned tf32u(float f){
    unsigned u; asm("cvt.rna.tf32.f32 %0, %1;" : "=r"(u) : "f"(f));
    return u;
}
__device__ __forceinline__ float tf32f(float f){ return __uint_as_float(tf32u(f)); }

__device__ __forceinline__ void mma8(float* d, const unsigned* a, unsigned b0, unsigned b1){
    asm volatile("mma.sync.aligned.m16n8k8.row.col.f32.tf32.tf32.f32 "
        "{%0,%1,%2,%3},{%4,%5,%6,%7},{%8,%9},{%0,%1,%2,%3};"
        : "+f"(d[0]),"+f"(d[1]),"+f"(d[2]),"+f"(d[3])
        : "r"(a[0]),"r"(a[1]),"r"(a[2]),"r"(a[3]),"r"(b0),"r"(b1));
}

__device__ __forceinline__ float fast_sigmoid(float x){
    return 1.f/(1.f + __expf(-x));
}
__device__ __forceinline__ float fast_tanh(float x){
    float ax = fabsf(x);
    float e  = __expf(2.f*ax);
    float th = 1.f - 2.f/(e + 1.f);
    return copysignf(th, x);
}

// software grid barrier (all NCTA CTAs co-resident by construction)
__device__ __forceinline__ void grid_barrier(){
    __syncthreads();
    if (threadIdx.x == 0){
        unsigned gen = atomicAdd(&g_bar_gen, 0u);
        unsigned t   = atomicAdd(&g_bar_cnt, 1u);
        if (t == NCTA-1){
            atomicExch(&g_bar_cnt, 0u);
            __threadfence();
            atomicAdd(&g_bar_gen, 1u);
        } else {
            while (atomicAdd(&g_bar_gen, 0u) == gen) { __nanosleep(32); }
        }
        __threadfence();
    }
    __syncthreads();
}

// ---------------- 1) XI = A @ W^T + bias  (tf32 mma, 128x128 tiles) ----------------
// A: [MR, K] row-major (optionally permuted view of x [B,T,IN]); W: [3072, K]; out: g_xi
// grid: (24 n-tiles, 512 m-tiles) -> n fastest => A panels + W stay L2-resident
__global__ void __launch_bounds__(256) k_gemm(const float* __restrict__ ext, int sel,
        const float* __restrict__ W, const float* __restrict__ bias,
        int K, int perm)
{
    __shared__ float As[2][128][20];
    __shared__ float Bs[2][128][20];

    const float* A = ext ? ext : (sel==1 ? g_hsA : g_hsB);

    const int tid = threadIdx.x;
    const int lane = tid&31, wid = tid>>5;
    const int g = lane>>2, tg = lane&3;
    const int wm = wid&3, wn = wid>>2;           // 4 x 2 warps, warp tile 32x64
    const int n0 = blockIdx.x*128, m0 = blockIdx.y*128;
    const int r0 = tid>>2, q0 = tid&3;

    int ra = m0 + r0, rb = m0 + r0 + 64;
    const float* Arow0 = (perm ? A + (((size_t)(ra&(Bsz-1)))*Tsz + (ra>>7))*K
                               : A + (size_t)ra*K) + q0*4;
    const float* Arow1 = (perm ? A + (((size_t)(rb&(Bsz-1)))*Tsz + (rb>>7))*K
                               : A + (size_t)rb*K) + q0*4;
    const float* Wrow0 = W + (size_t)(n0+r0   )*K + q0*4;
    const float* Wrow1 = W + (size_t)(n0+r0+64)*K + q0*4;

    float C[2][8][4] = {};

    {   // prologue: tile 0 -> buffer 0
        float4 a0=*(const float4*)Arow0, a1=*(const float4*)Arow1;
        float4 b0=*(const float4*)Wrow0, b1=*(const float4*)Wrow1;
        float* p;
        p=&As[0][r0   ][q0*4]; p[0]=tf32f(a0.x);p[1]=tf32f(a0.y);p[2]=tf32f(a0.z);p[3]=tf32f(a0.w);
        p=&As[0][r0+64][q0*4]; p[0]=tf32f(a1.x);p[1]=tf32f(a1.y);p[2]=tf32f(a1.z);p[3]=tf32f(a1.w);
        p=&Bs[0][r0   ][q0*4]; p[0]=tf32f(b0.x);p[1]=tf32f(b0.y);p[2]=tf32f(b0.z);p[3]=tf32f(b0.w);
        p=&Bs[0][r0+64][q0*4]; p[0]=tf32f(b1.x);p[1]=tf32f(b1.y);p[2]=tf32f(b1.z);p[3]=tf32f(b1.w);
    }
    __syncthreads();

    const int nkb = K>>4;
    float4 na0,na1,nb0,nb1;
    for (int kb=0; kb<nkb; ++kb){
        if (kb+1<nkb){
            int k0=(kb+1)<<4;
            na0=*(const float4*)(Arow0+k0); na1=*(const float4*)(Arow1+k0);
            nb0=*(const float4*)(Wrow0+k0); nb1=*(const float4*)(Wrow1+k0);
        }
        const int cur = kb&1;
        #pragma unroll
        for (int ks=0; ks<2; ++ks){
            const int kk = ks*8;
            unsigned a[2][4];
            #pragma unroll
            for (int mt=0; mt<2; ++mt){
                int row = wm*32+mt*16;
                a[mt][0]=__float_as_uint(As[cur][row+g  ][kk+tg  ]);
                a[mt][1]=__float_as_uint(As[cur][row+g+8][kk+tg  ]);
                a[mt][2]=__float_as_uint(As[cur][row+g  ][kk+tg+4]);
                a[mt][3]=__float_as_uint(As[cur][row+g+8][kk+tg+4]);
            }
            #pragma unroll
            for (int nt=0; nt<8; ++nt){
                int col = wn*64+nt*8+g;
                unsigned b0=__float_as_uint(Bs[cur][col][kk+tg  ]);
                unsigned b1=__float_as_uint(Bs[cur][col][kk+tg+4]);
                mma8(C[0][nt], a[0], b0, b1);
                mma8(C[1][nt], a[1], b0, b1);
            }
        }
        if (kb+1<nkb){
            const int nb=(kb+1)&1;
            float* p;
            p=&As[nb][r0   ][q0*4]; p[0]=tf32f(na0.x);p[1]=tf32f(na0.y);p[2]=tf32f(na0.z);p[3]=tf32f(na0.w);
            p=&As[nb][r0+64][q0*4]; p[0]=tf32f(na1.x);p[1]=tf32f(na1.y);p[2]=tf32f(na1.z);p[3]=tf32f(na1.w);
            p=&Bs[nb][r0   ][q0*4]; p[0]=tf32f(nb0.x);p[1]=tf32f(nb0.y);p[2]=tf32f(nb0.z);p[3]=tf32f(nb0.w);
            p=&Bs[nb][r0+64][q0*4]; p[0]=tf32f(nb1.x);p[1]=tf32f(nb1.y);p[2]=tf32f(nb1.z);p[3]=tf32f(nb1.w);
            __syncthreads();
        }
    }

    #pragma unroll
    for (int mt=0; mt<2; ++mt){
        #pragma unroll
        for (int nt=0; nt<8; ++nt){
            int row = m0 + wm*32 + mt*16 + g;
            int col = n0 + wn*64 + nt*8 + 2*tg;
            float bb0 = bias[col], bb1 = bias[col+1];
            float2 v;
            v.x = C[mt][nt][0]+bb0; v.y = C[mt][nt][1]+bb1;
            *(float2*)&g_xi[(size_t)row*G3sz+col] = v;
            v.x = C[mt][nt][2]+bb0; v.y = C[mt][nt][3]+bb1;
            *(float2*)&g_xi[(size_t)(row+8)*G3sz+col] = v;
        }
    }
}

// ---------------- 2) persistent GRU scan: 128 CTAs x 8 units, 512 steps ----------------
// hseq[t] = GRU(hseq[t-1], g_xi[t]); hseq selected by sel (1=g_hsA, 2=g_hsB)
__global__ void __launch_bounds__(256) k_scan(const float* __restrict__ whh,
        const float* __restrict__ bhh, int sel)
{
    extern __shared__ float sm[];
    float* Ws = sm;               // [GR][WS] tf32 gate rows of w_hh (r:0-7, z:8-15, n:16-23)
    float* bh = sm + GR*WS;       // [GR]     b_hh gate biases (pad to 32)
    float* Gs = bh + 32;          // [128][GS] per-step hidden-side gate values

    float* hs = (sel==1) ? g_hsA : g_hsB;
    const float* xi = g_xi;

    const int tid = threadIdx.x, bx = blockIdx.x;
    const int lane = tid&31, wid = tid>>5;
    const int g = lane>>2, tg = lane&3;
    const int m0 = wid*16;        // 8 warps split m: 16 batch rows each, all 24 cols

    // prologue: stage this CTA's 24 gate rows as tf32
    for (int r=0; r<GR; ++r){
        int gt=r>>3, u=r&7;     // gate, unit
        const float4* src = (const float4*)(whh + ((size_t)(gt*Hsz + bx*UPC + u))*Hsz);
        float4 v = src[tid];
        float* dst = Ws + r*WS + tid*4;
        dst[0]=tf32f(v.x); dst[1]=tf32f(v.y); dst[2]=tf32f(v.z); dst[3]=tf32f(v.w);
    }
    if (tid < GR){ int gt=tid>>3, u=tid&7; bh[tid] = bhh[gt*Hsz + bx*UPC + u]; }
    __syncthreads();

    const int eu = tid&7, eb0 = (tid>>3)*4;   // epilogue: unit, 4 batch rows
    const int ucol = bx*UPC + eu;

    for (int t=0; t<Tsz; ++t){
        if (t>0){
            float C[3][4] = {};
            const float* pa = hs + (size_t)(t-1)*BH + (size_t)(m0+g)*Hsz + tg;
            #pragma unroll 4
            for (int kk=0; kk<Hsz; kk+=8){
                unsigned a[4];
                const float* q = pa + kk;
                a[0]=tf32u(q[0]);  a[1]=tf32u(q[8*Hsz]);
                a[2]=tf32u(q[4]);  a[3]=tf32u(q[8*Hsz+4]);
                #pragma unroll
                for (int nt=0; nt<3; ++nt){
                    const float* wrow = Ws + (nt*8+g)*WS + kk + tg;
                    unsigned b0=__float_as_uint(wrow[0]);
                    unsigned b1=__float_as_uint(wrow[4]);
                    mma8(C[nt], a, b0, b1);
                }
            }
            #pragma unroll
            for (int nt=0; nt<3; ++nt){
                int row = m0+g, col = nt*8+2*tg;
                *(float2*)&Gs[row*GS+col]     = make_float2(C[nt][0], C[nt][1]);
                *(float2*)&Gs[(row+8)*GS+col] = make_float2(C[nt][2], C[nt][3]);
            }
        }
        __syncthreads();

        // epilogue: 4 (b,u) pairs per thread
        float br = bh[eu], bz = bh[UPC+eu], bn = bh[2*UPC+eu];
        #pragma unroll
        for (int i=0; i<4; ++i){
            int b = eb0 + i;
            size_t xbase = ((size_t)t*Bsz + b)*G3sz + bx*UPC + eu;
            float xr = xi[xbase], xz = xi[xbase+Hsz], xn = xi[xbase+2*Hsz];
            float Gr=0.f, Gz=0.f, Gn=0.f, hold=0.f;
            if (t>0){
                Gr = Gs[b*GS+eu]; Gz = Gs[b*GS+UPC+eu]; Gn = Gs[b*GS+2*UPC+eu];
                hold = hs[((size_t)(t-1)*Bsz + b)*Hsz + ucol];
            }
            float r  = fast_sigmoid(xr + Gr + br);
            float z  = fast_sigmoid(xz + Gz + bz);
            float nn = fast_tanh(xn + r*(Gn + bn));
            hs[((size_t)t*Bsz + b)*Hsz + ucol] = (1.f - z)*nn + z*hold;
        }

        if (t < Tsz-1){
            __threadfence();
            grid_barrier();
        }
    }
}

// ---------------- 3) FC: out[b][p] = h_last[b] . fc_w[p] + fc_b[p] ----------------
__global__ void k_fc(const float* __restrict__ fw, const float* __restrict__ fb,
                     float* __restrict__ out)
{
    __shared__ float w[Hsz];
    const int p = blockIdx.x, b = threadIdx.x;
    for (int k=b; k<Hsz; k+=Bsz) w[k] = fw[(size_t)p*Hsz + k];
    __syncthreads();
    const float* h = g_hsA + ((size_t)(Tsz-1)*Bsz + b)*Hsz;
    float s = 0.f;
    #pragma unroll 8
    for (int k=0; k<Hsz; ++k) s += h[k]*w[k];
    out[b*PREDsz + p] = s + fb[p];
}

// ---------------- launch ----------------
extern "C" void kernel_launch(void* const* d_in, const int* in_sizes, int n_in,
                              void* d_out, int out_size)
{
    const float* x    = (const float*)d_in[0];
    const float* wih0 = (const float*)d_in[1];
    const float* whh0 = (const float*)d_in[2];
    const float* bih0 = (const float*)d_in[3];
    const float* bhh0 = (const float*)d_in[4];
    const float* wih1 = (const float*)d_in[5];
    const float* whh1 = (const float*)d_in[6];
    const float* bih1 = (const float*)d_in[7];
    const float* bhh1 = (const float*)d_in[8];
    const float* wih2 = (const float*)d_in[9];
    const float* whh2 = (const float*)d_in[10];
    const float* bih2 = (const float*)d_in[11];
    const float* bhh2 = (const float*)d_in[12];
    const float* fcw  = (const float*)d_in[13];
    const float* fcb  = (const float*)d_in[14];
    float* out = (float*)d_out;

    cudaFuncSetAttribute(k_scan, cudaFuncAttributeMaxDynamicSharedMemorySize, SCAN_SMEM_BYTES);

    dim3 gg(G3sz/128, MR/128);   // n fastest for L2 reuse

    // layer 0 (input x, permuted [B,T,IN] -> row t*B+b)
    k_gemm<<<gg, 256>>>(x, 0, wih0, bih0, INsz, 1);
    k_scan<<<NCTA, 256, SCAN_SMEM_BYTES>>>(whh0, bhh0, 1);
    // layer 1
    k_gemm<<<gg, 256>>>(nullptr, 1, wih1, bih1, Hsz, 0);
    k_scan<<<NCTA, 256, SCAN_SMEM_BYTES>>>(whh1, bhh1, 2);
    // layer 2
    k_gemm<<<gg, 256>>>(nullptr, 2, wih2, bih2, Hsz, 0);
    k_scan<<<NCTA, 256, SCAN_SMEM_BYTES>>>(whh2, bhh2, 1);
    // head
    k_fc<<<PREDsz, Bsz>>>(fcw, fcb, out);
}

// round 5
// speedup vs baseline: 1.6338x; 1.6338x over previous
#include <cuda_runtime.h>
#include <cuda_bf16.h>
#include <cstdint>

// Problem dims
#define Bsz   128
#define Tsz   512
#define INsz  128
#define Hsz   1024
#define G3sz  3072
#define PREDsz 96
#define MR    (Tsz*Bsz)        // 65536 rows
#define BH    (Bsz*Hsz)        // 131072

// Scan kernel config: 128 persistent CTAs, 8 hidden units each
#define NCTA  128
#define UPC   8                // units per CTA
#define GR    (3*UPC)          // gate rows per CTA = 24
#define WS    1028             // smem weight row stride (floats), conflict-free
#define GS    26               // smem gate buffer row stride (floats)
// h staging: 64-column chunks, 3-buffer ring
#define CH    64
#define NCH   (Hsz/CH)         // 16
#define HST   (CH+4)           // 68 floats row stride (bank-conflict free)
#define BUFSZ (Bsz*HST)        // 8704 floats per buffer
#define SCAN_SMEM_FLOATS (GR*WS + 32 + Bsz*GS + 3*BUFSZ)
#define SCAN_SMEM_BYTES  (SCAN_SMEM_FLOATS*4)   // 216576 B

// ---------------- device scratch (allocation-free rule) ----------------
__device__ float g_xi [(size_t)MR*G3sz];   // [T,B,3H] input-side gate projections
__device__ float g_hsA[(size_t)MR*Hsz];    // [T,B,H] hidden sequence buffer A
__device__ float g_hsB[(size_t)MR*Hsz];    // [T,B,H] hidden sequence buffer B
__device__ unsigned g_bar_cnt = 0;
__device__ unsigned g_bar_gen = 0;

// ---------------- helpers ----------------
__device__ __forceinline__ unsigned tf32u(float f){
    unsigned u; asm("cvt.rna.tf32.f32 %0, %1;" : "=r"(u) : "f"(f));
    return u;
}
__device__ __forceinline__ float tf32f(float f){ return __uint_as_float(tf32u(f)); }

__device__ __forceinline__ void mma8(float* d, const unsigned* a, unsigned b0, unsigned b1){
    asm volatile("mma.sync.aligned.m16n8k8.row.col.f32.tf32.tf32.f32 "
        "{%0,%1,%2,%3},{%4,%5,%6,%7},{%8,%9},{%0,%1,%2,%3};"
        : "+f"(d[0]),"+f"(d[1]),"+f"(d[2]),"+f"(d[3])
        : "r"(a[0]),"r"(a[1]),"r"(a[2]),"r"(a[3]),"r"(b0),"r"(b1));
}

__device__ __forceinline__ float fast_sigmoid(float x){
    return 1.f/(1.f + __expf(-x));
}
__device__ __forceinline__ float fast_tanh(float x){
    float ax = fabsf(x);
    float e  = __expf(2.f*ax);
    float th = 1.f - 2.f/(e + 1.f);
    return copysignf(th, x);
}

// software grid barrier (all NCTA CTAs co-resident by construction)
__device__ __forceinline__ void grid_barrier(){
    __syncthreads();
    if (threadIdx.x == 0){
        unsigned gen = atomicAdd(&g_bar_gen, 0u);
        unsigned t   = atomicAdd(&g_bar_cnt, 1u);
        if (t == NCTA-1){
            atomicExch(&g_bar_cnt, 0u);
            __threadfence();
            atomicAdd(&g_bar_gen, 1u);
        } else {
            while (atomicAdd(&g_bar_gen, 0u) == gen) { __nanosleep(32); }
        }
        __threadfence();
    }
    __syncthreads();
}

// ---------------- 1) XI = A @ W^T + bias  (tf32 mma, 128x128 tiles) ----------------
__global__ void __launch_bounds__(256) k_gemm(const float* __restrict__ ext, int sel,
        const float* __restrict__ W, const float* __restrict__ bias,
        int K, int perm)
{
    __shared__ float As[2][128][20];
    __shared__ float Bs[2][128][20];

    const float* A = ext ? ext : (sel==1 ? g_hsA : g_hsB);

    const int tid = threadIdx.x;
    const int lane = tid&31, wid = tid>>5;
    const int g = lane>>2, tg = lane&3;
    const int wm = wid&3, wn = wid>>2;           // 4 x 2 warps, warp tile 32x64
    const int n0 = blockIdx.x*128, m0 = blockIdx.y*128;
    const int r0 = tid>>2, q0 = tid&3;

    int ra = m0 + r0, rb = m0 + r0 + 64;
    const float* Arow0 = (perm ? A + (((size_t)(ra&(Bsz-1)))*Tsz + (ra>>7))*K
                               : A + (size_t)ra*K) + q0*4;
    const float* Arow1 = (perm ? A + (((size_t)(rb&(Bsz-1)))*Tsz + (rb>>7))*K
                               : A + (size_t)rb*K) + q0*4;
    const float* Wrow0 = W + (size_t)(n0+r0   )*K + q0*4;
    const float* Wrow1 = W + (size_t)(n0+r0+64)*K + q0*4;

    float C[2][8][4] = {};

    {   // prologue: tile 0 -> buffer 0
        float4 a0=*(const float4*)Arow0, a1=*(const float4*)Arow1;
        float4 b0=*(const float4*)Wrow0, b1=*(const float4*)Wrow1;
        float* p;
        p=&As[0][r0   ][q0*4]; p[0]=tf32f(a0.x);p[1]=tf32f(a0.y);p[2]=tf32f(a0.z);p[3]=tf32f(a0.w);
        p=&As[0][r0+64][q0*4]; p[0]=tf32f(a1.x);p[1]=tf32f(a1.y);p[2]=tf32f(a1.z);p[3]=tf32f(a1.w);
        p=&Bs[0][r0   ][q0*4]; p[0]=tf32f(b0.x);p[1]=tf32f(b0.y);p[2]=tf32f(b0.z);p[3]=tf32f(b0.w);
        p=&Bs[0][r0+64][q0*4]; p[0]=tf32f(b1.x);p[1]=tf32f(b1.y);p[2]=tf32f(b1.z);p[3]=tf32f(b1.w);
    }
    __syncthreads();

    const int nkb = K>>4;
    float4 na0,na1,nb0,nb1;
    for (int kb=0; kb<nkb; ++kb){
        if (kb+1<nkb){
            int k0=(kb+1)<<4;
            na0=*(const float4*)(Arow0+k0); na1=*(const float4*)(Arow1+k0);
            nb0=*(const float4*)(Wrow0+k0); nb1=*(const float4*)(Wrow1+k0);
        }
        const int cur = kb&1;
        #pragma unroll
        for (int ks=0; ks<2; ++ks){
            const int kk = ks*8;
            unsigned a[2][4];
            #pragma unroll
            for (int mt=0; mt<2; ++mt){
                int row = wm*32+mt*16;
                a[mt][0]=__float_as_uint(As[cur][row+g  ][kk+tg  ]);
                a[mt][1]=__float_as_uint(As[cur][row+g+8][kk+tg  ]);
                a[mt][2]=__float_as_uint(As[cur][row+g  ][kk+tg+4]);
                a[mt][3]=__float_as_uint(As[cur][row+g+8][kk+tg+4]);
            }
            #pragma unroll
            for (int nt=0; nt<8; ++nt){
                int col = wn*64+nt*8+g;
                unsigned b0=__float_as_uint(Bs[cur][col][kk+tg  ]);
                unsigned b1=__float_as_uint(Bs[cur][col][kk+tg+4]);
                mma8(C[0][nt], a[0], b0, b1);
                mma8(C[1][nt], a[1], b0, b1);
            }
        }
        if (kb+1<nkb){
            const int nb=(kb+1)&1;
            float* p;
            p=&As[nb][r0   ][q0*4]; p[0]=tf32f(na0.x);p[1]=tf32f(na0.y);p[2]=tf32f(na0.z);p[3]=tf32f(na0.w);
            p=&As[nb][r0+64][q0*4]; p[0]=tf32f(na1.x);p[1]=tf32f(na1.y);p[2]=tf32f(na1.z);p[3]=tf32f(na1.w);
            p=&Bs[nb][r0   ][q0*4]; p[0]=tf32f(nb0.x);p[1]=tf32f(nb0.y);p[2]=tf32f(nb0.z);p[3]=tf32f(nb0.w);
            p=&Bs[nb][r0+64][q0*4]; p[0]=tf32f(nb1.x);p[1]=tf32f(nb1.y);p[2]=tf32f(nb1.z);p[3]=tf32f(nb1.w);
            __syncthreads();
        }
    }

    #pragma unroll
    for (int mt=0; mt<2; ++mt){
        #pragma unroll
        for (int nt=0; nt<8; ++nt){
            int row = m0 + wm*32 + mt*16 + g;
            int col = n0 + wn*64 + nt*8 + 2*tg;
            float bb0 = bias[col], bb1 = bias[col+1];
            float2 v;
            v.x = C[mt][nt][0]+bb0; v.y = C[mt][nt][1]+bb1;
            *(float2*)&g_xi[(size_t)row*G3sz+col] = v;
            v.x = C[mt][nt][2]+bb0; v.y = C[mt][nt][3]+bb1;
            *(float2*)&g_xi[(size_t)(row+8)*G3sz+col] = v;
        }
    }
}

// ---------------- 2) persistent GRU scan v2: cp.async-staged h ----------------
__device__ __forceinline__ void stage_chunk(const float* __restrict__ hb, int c,
                                            float* dstbuf, int tid){
    #pragma unroll
    for (int j=0;j<8;++j){
        int idx = tid + j*256;
        int row = idx>>4, c4 = idx&15;
        const float* src = hb + (size_t)row*Hsz + c*CH + c4*4;
        unsigned dst = (unsigned)__cvta_generic_to_shared(dstbuf + row*HST + c4*4);
        asm volatile("cp.async.cg.shared.global [%0], [%1], 16;" :: "r"(dst), "l"(src));
    }
    asm volatile("cp.async.commit_group;" ::: "memory");
}

__global__ void __launch_bounds__(256) k_scan(const float* __restrict__ whh,
        const float* __restrict__ bhh, int sel)
{
    extern __shared__ float sm[];
    float* Ws = sm;                      // [GR][WS] tf32 gate rows (r:0-7, z:8-15, n:16-23)
    float* bh = sm + GR*WS;              // [GR] biases (pad 32)
    float* Gs = bh + 32;                 // [128][GS] hidden-side gate values
    float* Hb = Gs + Bsz*GS;             // [3][128][HST] staged h chunks

    float* hs = (sel==1) ? g_hsA : g_hsB;
    const float* xi = g_xi;

    const int tid = threadIdx.x, bx = blockIdx.x;
    const int lane = tid&31, wid = tid>>5;
    const int g = lane>>2, tg = lane&3;
    const int m0 = wid*16;               // 8 warps split m: 16 batch rows each

    // prologue: stage this CTA's 24 gate rows as tf32
    for (int r=0; r<GR; ++r){
        int gt=r>>3, u=r&7;
        const float4* src = (const float4*)(whh + ((size_t)(gt*Hsz + bx*UPC + u))*Hsz);
        float4 v = src[tid];
        float* dst = Ws + r*WS + tid*4;
        dst[0]=tf32f(v.x); dst[1]=tf32f(v.y); dst[2]=tf32f(v.z); dst[3]=tf32f(v.w);
    }
    if (tid < GR){ int gt=tid>>3, u=tid&7; bh[tid] = bhh[gt*Hsz + bx*UPC + u]; }
    __syncthreads();

    const int eu = tid&7, eb0 = (tid>>3)*4;   // epilogue: unit, 4 batch rows
    const int ucol = bx*UPC + eu;

    for (int t=0; t<Tsz; ++t){
        const float* hb = hs + (size_t)(t-1)*BH;   // valid when t>0

        // prefetch epilogue inputs (latency hides under mma phase)
        float pxr[4], pxz[4], pxn[4], ph[4];
        #pragma unroll
        for (int i=0;i<4;++i){
            int b = eb0 + i;
            const float* xb = xi + ((size_t)t*Bsz + b)*G3sz + bx*UPC + eu;
            pxr[i]=xb[0]; pxz[i]=xb[Hsz]; pxn[i]=xb[2*Hsz];
            ph[i] = (t>0) ? hb[(size_t)b*Hsz + ucol] : 0.f;
        }

        if (t>0){
            float C[3][4] = {};
            stage_chunk(hb, 0, Hb,          tid);
            stage_chunk(hb, 1, Hb + BUFSZ,  tid);
            for (int c=0; c<NCH; ++c){
                if (c == NCH-1) asm volatile("cp.async.wait_group 0;" ::: "memory");
                else            asm volatile("cp.async.wait_group 1;" ::: "memory");
                __syncthreads();   // chunk c visible to all; all warps done reading c-1's ring slot
                if (c+2 < NCH) stage_chunk(hb, c+2, Hb + ((c+2)%3)*BUFSZ, tid);
                const float* war = Hb + (c%3)*BUFSZ + (m0+g)*HST + tg;
                const int kcol0 = c*CH;
                #pragma unroll
                for (int kk=0; kk<CH; kk+=8){
                    unsigned a[4];
                    a[0]=tf32u(war[kk]);        a[1]=tf32u(war[8*HST+kk]);
                    a[2]=tf32u(war[kk+4]);      a[3]=tf32u(war[8*HST+kk+4]);
                    #pragma unroll
                    for (int nt=0; nt<3; ++nt){
                        const float* wr = Ws + (nt*8+g)*WS + kcol0 + kk + tg;
                        unsigned b0=__float_as_uint(wr[0]);
                        unsigned b1=__float_as_uint(wr[4]);
                        mma8(C[nt], a, b0, b1);
                    }
                }
            }
            #pragma unroll
            for (int nt=0; nt<3; ++nt){
                int row = m0+g, col = nt*8+2*tg;
                *(float2*)&Gs[row*GS+col]     = make_float2(C[nt][0], C[nt][1]);
                *(float2*)&Gs[(row+8)*GS+col] = make_float2(C[nt][2], C[nt][3]);
            }
        }
        __syncthreads();

        // epilogue: 4 (b,u) pairs per thread
        float br = bh[eu], bz = bh[UPC+eu], bn = bh[2*UPC+eu];
        #pragma unroll
        for (int i=0; i<4; ++i){
            int b = eb0 + i;
            float Gr=0.f, Gz=0.f, Gn=0.f;
            if (t>0){
                Gr = Gs[b*GS+eu]; Gz = Gs[b*GS+UPC+eu]; Gn = Gs[b*GS+2*UPC+eu];
            }
            float r  = fast_sigmoid(pxr[i] + Gr + br);
            float z  = fast_sigmoid(pxz[i] + Gz + bz);
            float nn = fast_tanh(pxn[i] + r*(Gn + bn));
            hs[((size_t)t*Bsz + b)*Hsz + ucol] = (1.f - z)*nn + z*ph[i];
        }

        if (t < Tsz-1){
            __threadfence();
            grid_barrier();
        }
    }
}

// ---------------- 3) FC: out[b][p] = h_last[b] . fc_w[p] + fc_b[p] ----------------
__global__ void k_fc(const float* __restrict__ fw, const float* __restrict__ fb,
                     float* __restrict__ out)
{
    __shared__ float w[Hsz];
    const int p = blockIdx.x, b = threadIdx.x;
    for (int k=b; k<Hsz; k+=Bsz) w[k] = fw[(size_t)p*Hsz + k];
    __syncthreads();
    const float* h = g_hsA + ((size_t)(Tsz-1)*Bsz + b)*Hsz;
    float s = 0.f;
    #pragma unroll 8
    for (int k=0; k<Hsz; ++k) s += h[k]*w[k];
    out[b*PREDsz + p] = s + fb[p];
}

// ---------------- launch ----------------
extern "C" void kernel_launch(void* const* d_in, const int* in_sizes, int n_in,
                              void* d_out, int out_size)
{
    const float* x    = (const float*)d_in[0];
    const float* wih0 = (const float*)d_in[1];
    const float* whh0 = (const float*)d_in[2];
    const float* bih0 = (const float*)d_in[3];
    const float* bhh0 = (const float*)d_in[4];
    const float* wih1 = (const float*)d_in[5];
    const float* whh1 = (const float*)d_in[6];
    const float* bih1 = (const float*)d_in[7];
    const float* bhh1 = (const float*)d_in[8];
    const float* wih2 = (const float*)d_in[9];
    const float* whh2 = (const float*)d_in[10];
    const float* bih2 = (const float*)d_in[11];
    const float* bhh2 = (const float*)d_in[12];
    const float* fcw  = (const float*)d_in[13];
    const float* fcb  = (const float*)d_in[14];
    float* out = (float*)d_out;

    cudaFuncSetAttribute(k_scan, cudaFuncAttributeMaxDynamicSharedMemorySize, SCAN_SMEM_BYTES);

    dim3 gg(G3sz/128, MR/128);   // n fastest for L2 reuse

    // layer 0 (input x, permuted [B,T,IN] -> row t*B+b)
    k_gemm<<<gg, 256>>>(x, 0, wih0, bih0, INsz, 1);
    k_scan<<<NCTA, 256, SCAN_SMEM_BYTES>>>(whh0, bhh0, 1);
    // layer 1
    k_gemm<<<gg, 256>>>(nullptr, 1, wih1, bih1, Hsz, 0);
    k_scan<<<NCTA, 256, SCAN_SMEM_BYTES>>>(whh1, bhh1, 2);
    // layer 2
    k_gemm<<<gg, 256>>>(nullptr, 2, wih2, bih2, Hsz, 0);
    k_scan<<<NCTA, 256, SCAN_SMEM_BYTES>>>(whh2, bhh2, 1);
    // head
    k_fc<<<PREDsz, Bsz>>>(fcw, fcb, out);
}

// round 7
// speedup vs baseline: 2.4268x; 1.4853x over previous
#include <cuda_runtime.h>
#include <cuda_bf16.h>
#include <cstdint>

// Problem dims
#define Bsz   128
#define Tsz   512
#define INsz  128
#define Hsz   1024
#define G3sz  3072
#define PREDsz 96
#define MR    (Tsz*Bsz)        // 65536 rows
#define BH    (Bsz*Hsz)        // 131072

// Scan kernel config: 128 persistent CTAs, 8 hidden units each, 16 warps (split-K 2)
#define NCTA  128
#define UPC   8                // units per CTA
#define GR    (3*UPC)          // gate rows per CTA = 24
#define WST2  516              // Wp row stride in float2 (conflict-free LDS.64)
#define GS    26               // Gs row stride (floats)
#define CH    32               // staging chunk columns
#define NCH   16               // chunks per K-half (512/32)
#define HST2  36               // staging row stride (floats)
#define WBUF  (16*HST2)        // 576 floats: one 16-row staging buffer
// SMEM map (floats): Wp | bias | Gs[2] | Hb[16 warps][2 bufs]
#define OFF_BH   (GR*WST2*2)                 // 24768
#define OFF_GS   (OFF_BH + 32)               // 24800
#define OFF_HB   (OFF_GS + 2*Bsz*GS)         // 31456
#define SCAN_SMEM_FLOATS (OFF_HB + 16*2*WBUF) // 49888
#define SCAN_SMEM_BYTES  (SCAN_SMEM_FLOATS*4) // 199552 B

// ---------------- device scratch (allocation-free rule) ----------------
__device__ float g_xi [(size_t)MR*G3sz];   // [T,B,3H] input-side gate projections
__device__ float g_hsA[(size_t)MR*Hsz];    // [T,B,H] hidden sequence buffer A
__device__ float g_hsB[(size_t)MR*Hsz];    // [T,B,H] hidden sequence buffer B
__device__ unsigned g_bar_cnt = 0;
__device__ unsigned g_bar_gen = 0;

// ---------------- helpers ----------------
__device__ __forceinline__ unsigned tf32u(float f){
    unsigned u; asm("cvt.rna.tf32.f32 %0, %1;" : "=r"(u) : "f"(f));
    return u;
}
__device__ __forceinline__ float tf32f(float f){ return __uint_as_float(tf32u(f)); }

__device__ __forceinline__ void mma8(float* d, const unsigned* a, unsigned b0, unsigned b1){
    asm volatile("mma.sync.aligned.m16n8k8.row.col.f32.tf32.tf32.f32 "
        "{%0,%1,%2,%3},{%4,%5,%6,%7},{%8,%9},{%0,%1,%2,%3};"
        : "+f"(d[0]),"+f"(d[1]),"+f"(d[2]),"+f"(d[3])
        : "r"(a[0]),"r"(a[1]),"r"(a[2]),"r"(a[3]),"r"(b0),"r"(b1));
}

__device__ __forceinline__ float fast_sigmoid(float x){
    return 1.f/(1.f + __expf(-x));
}
__device__ __forceinline__ float fast_tanh(float x){
    float ax = fabsf(x);
    float e  = __expf(2.f*ax);
    float th = 1.f - 2.f/(e + 1.f);
    return copysignf(th, x);
}

// software grid barrier (all NCTA CTAs co-resident by construction)
__device__ __forceinline__ void grid_barrier(){
    __syncthreads();
    if (threadIdx.x == 0){
        unsigned gen = atomicAdd(&g_bar_gen, 0u);
        unsigned t   = atomicAdd(&g_bar_cnt, 1u);
        if (t == NCTA-1){
            atomicExch(&g_bar_cnt, 0u);
            __threadfence();
            atomicAdd(&g_bar_gen, 1u);
        } else {
            while (atomicAdd(&g_bar_gen, 0u) == gen) { __nanosleep(32); }
        }
        __threadfence();
    }
    __syncthreads();
}

// ---------------- 1) XI = A @ W^T + bias  (tf32 mma, 128x128 tiles) ----------------
__global__ void __launch_bounds__(256) k_gemm(const float* __restrict__ ext, int sel,
        const float* __restrict__ W, const float* __restrict__ bias,
        int K, int perm)
{
    __shared__ float As[2][128][20];
    __shared__ float Bs[2][128][20];

    const float* A = ext ? ext : (sel==1 ? g_hsA : g_hsB);

    const int tid = threadIdx.x;
    const int lane = tid&31, wid = tid>>5;
    const int g = lane>>2, tg = lane&3;
    const int wm = wid&3, wn = wid>>2;           // 4 x 2 warps, warp tile 32x64
    const int n0 = blockIdx.x*128, m0 = blockIdx.y*128;
    const int r0 = tid>>2, q0 = tid&3;

    int ra = m0 + r0, rb = m0 + r0 + 64;
    const float* Arow0 = (perm ? A + (((size_t)(ra&(Bsz-1)))*Tsz + (ra>>7))*K
                               : A + (size_t)ra*K) + q0*4;
    const float* Arow1 = (perm ? A + (((size_t)(rb&(Bsz-1)))*Tsz + (rb>>7))*K
                               : A + (size_t)rb*K) + q0*4;
    const float* Wrow0 = W + (size_t)(n0+r0   )*K + q0*4;
    const float* Wrow1 = W + (size_t)(n0+r0+64)*K + q0*4;

    float C[2][8][4] = {};

    {   // prologue: tile 0 -> buffer 0
        float4 a0=*(const float4*)Arow0, a1=*(const float4*)Arow1;
        float4 b0=*(const float4*)Wrow0, b1=*(const float4*)Wrow1;
        float* p;
        p=&As[0][r0   ][q0*4]; p[0]=tf32f(a0.x);p[1]=tf32f(a0.y);p[2]=tf32f(a0.z);p[3]=tf32f(a0.w);
        p=&As[0][r0+64][q0*4]; p[0]=tf32f(a1.x);p[1]=tf32f(a1.y);p[2]=tf32f(a1.z);p[3]=tf32f(a1.w);
        p=&Bs[0][r0   ][q0*4]; p[0]=tf32f(b0.x);p[1]=tf32f(b0.y);p[2]=tf32f(b0.z);p[3]=tf32f(b0.w);
        p=&Bs[0][r0+64][q0*4]; p[0]=tf32f(b1.x);p[1]=tf32f(b1.y);p[2]=tf32f(b1.z);p[3]=tf32f(b1.w);
    }
    __syncthreads();

    const int nkb = K>>4;
    float4 na0,na1,nb0,nb1;
    for (int kb=0; kb<nkb; ++kb){
        if (kb+1<nkb){
            int k0=(kb+1)<<4;
            na0=*(const float4*)(Arow0+k0); na1=*(const float4*)(Arow1+k0);
            nb0=*(const float4*)(Wrow0+k0); nb1=*(const float4*)(Wrow1+k0);
        }
        const int cur = kb&1;
        #pragma unroll
        for (int ks=0; ks<2; ++ks){
            const int kk = ks*8;
            unsigned a[2][4];
            #pragma unroll
            for (int mt=0; mt<2; ++mt){
                int row = wm*32+mt*16;
                a[mt][0]=__float_as_uint(As[cur][row+g  ][kk+tg  ]);
                a[mt][1]=__float_as_uint(As[cur][row+g+8][kk+tg  ]);
                a[mt][2]=__float_as_uint(As[cur][row+g  ][kk+tg+4]);
                a[mt][3]=__float_as_uint(As[cur][row+g+8][kk+tg+4]);
            }
            #pragma unroll
            for (int nt=0; nt<8; ++nt){
                int col = wn*64+nt*8+g;
                unsigned b0=__float_as_uint(Bs[cur][col][kk+tg  ]);
                unsigned b1=__float_as_uint(Bs[cur][col][kk+tg+4]);
                mma8(C[0][nt], a[0], b0, b1);
                mma8(C[1][nt], a[1], b0, b1);
            }
        }
        if (kb+1<nkb){
            const int nb=(kb+1)&1;
            float* p;
            p=&As[nb][r0   ][q0*4]; p[0]=tf32f(na0.x);p[1]=tf32f(na0.y);p[2]=tf32f(na0.z);p[3]=tf32f(na0.w);
            p=&As[nb][r0+64][q0*4]; p[0]=tf32f(na1.x);p[1]=tf32f(na1.y);p[2]=tf32f(na1.z);p[3]=tf32f(na1.w);
            p=&Bs[nb][r0   ][q0*4]; p[0]=tf32f(nb0.x);p[1]=tf32f(nb0.y);p[2]=tf32f(nb0.z);p[3]=tf32f(nb0.w);
            p=&Bs[nb][r0+64][q0*4]; p[0]=tf32f(nb1.x);p[1]=tf32f(nb1.y);p[2]=tf32f(nb1.z);p[3]=tf32f(nb1.w);
            __syncthreads();
        }
    }

    #pragma unroll
    for (int mt=0; mt<2; ++mt){
        #pragma unroll
        for (int nt=0; nt<8; ++nt){
            int row = m0 + wm*32 + mt*16 + g;
            int col = n0 + wn*64 + nt*8 + 2*tg;
            float bb0 = bias[col], bb1 = bias[col+1];
            float2 v;
            v.x = C[mt][nt][0]+bb0; v.y = C[mt][nt][1]+bb1;
            *(float2*)&g_xi[(size_t)row*G3sz+col] = v;
            v.x = C[mt][nt][2]+bb0; v.y = C[mt][nt][3]+bb1;
            *(float2*)&g_xi[(size_t)(row+8)*G3sz+col] = v;
        }
    }
}

// ---------------- 2) persistent GRU scan v3: 16 warps, split-K, per-warp rings ----------------
__device__ __forceinline__ void stage2(const float* __restrict__ hb, int m0, int kg0,
                                       float* buf, int lane){
    #pragma unroll
    for (int j=0;j<4;++j){
        int idx = lane + j*32;          // 0..127 : 16 rows x 8 segs(16B)
        int row = idx>>3, c4 = idx&7;
        const float* src = hb + (size_t)(m0+row)*Hsz + kg0 + c4*4;
        unsigned dst = (unsigned)__cvta_generic_to_shared(buf + row*HST2 + c4*4);
        asm volatile("cp.async.cg.shared.global [%0], [%1], 16;" :: "r"(dst), "l"(src));
    }
    asm volatile("cp.async.commit_group;" ::: "memory");
}

__global__ void __launch_bounds__(512) k_scan(const float* __restrict__ whh,
        const float* __restrict__ bhh, int sel)
{
    extern __shared__ float sm[];
    float2* Wp = (float2*)sm;              // [GR][WST2] fragment-paired tf32 w_hh
    float*  bh = sm + OFF_BH;              // [GR] biases
    float*  Gs = sm + OFF_GS;              // [2][128][GS] split-K partial gates
    float*  Hb = sm + OFF_HB;              // [16][2][WBUF] per-warp staging rings

    float* hs = (sel==1) ? g_hsA : g_hsB;
    const float* xi = g_xi;

    const int tid = threadIdx.x, bx = blockIdx.x;
    const int lane = tid&31, wid = tid>>5;
    const int g = lane>>2, tg = lane&3;
    const int kh = wid&1, mg = wid>>1;     // K-half, m-group
    const int m0 = mg*16;
    const int kbase = kh*512;
    float* mybuf = Hb + wid*(2*WBUF);
    float* Gmy   = Gs + kh*(Bsz*GS);

    // prologue: fragment-paired tf32 weights (pair = k elems {kk+tg, kk+tg+4})
    for (int idx = tid; idx < GR*512; idx += 512){
        int r = idx>>9, p = idx&511;
        int k0 = (p>>2)<<3, tp = p&3;
        int gt = r>>3, u = r&7;
        const float* w = whh + ((size_t)(gt*Hsz + bx*UPC + u))*Hsz;
        Wp[r*WST2 + (p>>2)*4 + tp] = make_float2(tf32f(w[k0+tp]), tf32f(w[k0+tp+4]));
    }
    if (tid < GR){ int gt=tid>>3, u=tid&7; bh[tid] = bhh[gt*Hsz + bx*UPC + u]; }
    __syncthreads();

    const int eu = tid&7, eb0 = (tid>>3)*2;   // epilogue: unit, 2 batch rows
    const int ucol = bx*UPC + eu;

    for (int t=0; t<Tsz; ++t){
        const float* hb = hs + (size_t)(t-1)*BH;   // deref'd only when t>0

        // prefetch epilogue inputs (latency hides under mma phase)
        float pxr[2], pxz[2], pxn[2], ph[2];
        #pragma unroll
        for (int i=0;i<2;++i){
            int b = eb0 + i;
            const float* xb = xi + ((size_t)t*Bsz + b)*G3sz + bx*UPC + eu;
            pxr[i]=xb[0]; pxz[i]=xb[Hsz]; pxn[i]=xb[2*Hsz];
            ph[i] = (t>0) ? hb[(size_t)b*Hsz + ucol] : 0.f;
        }

        if (t>0){
            float C[3][4] = {};
            stage2(hb, m0, kbase, mybuf, lane);
            for (int c=0; c<NCH; ++c){
                if (c+1 < NCH){
                    stage2(hb, m0, kbase + (c+1)*CH, mybuf + ((c+1)&1)*WBUF, lane);
                    asm volatile("cp.async.wait_group 1;" ::: "memory");
                } else {
                    asm volatile("cp.async.wait_group 0;" ::: "memory");
                }
                __syncwarp();
                const float* war = mybuf + (c&1)*WBUF + g*HST2 + tg;
                const int kp0 = ((kbase + c*CH)>>3)*4 + tg;
                #pragma unroll
                for (int kk=0; kk<CH; kk+=8){
                    unsigned a[4];
                    a[0]=tf32u(war[kk]);      a[1]=tf32u(war[8*HST2+kk]);
                    a[2]=tf32u(war[kk+4]);    a[3]=tf32u(war[8*HST2+kk+4]);
                    const int kp = kp0 + (kk>>3)*4;
                    #pragma unroll
                    for (int nt=0; nt<3; ++nt){
                        float2 bp = Wp[(nt*8+g)*WST2 + kp];
                        mma8(C[nt], a, __float_as_uint(bp.x), __float_as_uint(bp.y));
                    }
                }
            }
            #pragma unroll
            for (int nt=0; nt<3; ++nt){
                int row = m0+g, col = nt*8+2*tg;
                *(float2*)&Gmy[row*GS+col]     = make_float2(C[nt][0], C[nt][1]);
                *(float2*)&Gmy[(row+8)*GS+col] = make_float2(C[nt][2], C[nt][3]);
            }
        }
        __syncthreads();

        // epilogue: 2 (b,u) pairs per thread; sum the two split-K partials
        float br = bh[eu], bz = bh[UPC+eu], bn = bh[2*UPC+eu];
        #pragma unroll
        for (int i=0; i<2; ++i){
            int b = eb0 + i;
            float Gr=0.f, Gz=0.f, Gn=0.f;
            if (t>0){
                Gr = Gs[b*GS+eu]       + Gs[Bsz*GS + b*GS+eu];
                Gz = Gs[b*GS+UPC+eu]   + Gs[Bsz*GS + b*GS+UPC+eu];
                Gn = Gs[b*GS+2*UPC+eu] + Gs[Bsz*GS + b*GS+2*UPC+eu];
            }
            float r  = fast_sigmoid(pxr[i] + Gr + br);
            float z  = fast_sigmoid(pxz[i] + Gz + bz);
            float nn = fast_tanh(pxn[i] + r*(Gn + bn));
            hs[((size_t)t*Bsz + b)*Hsz + ucol] = (1.f - z)*nn + z*ph[i];
        }

        if (t < Tsz-1){
            __threadfence();
            grid_barrier();
        }
    }
}

// ---------------- 3) FC: out[b][p] = h_last[b] . fc_w[p] + fc_b[p] ----------------
__global__ void k_fc(const float* __restrict__ fw, const float* __restrict__ fb,
                     float* __restrict__ out)
{
    __shared__ float w[Hsz];
    const int p = blockIdx.x, b = threadIdx.x;
    for (int k=b; k<Hsz; k+=Bsz) w[k] = fw[(size_t)p*Hsz + k];
    __syncthreads();
    const float* h = g_hsA + ((size_t)(Tsz-1)*Bsz + b)*Hsz;
    float s = 0.f;
    #pragma unroll 8
    for (int k=0; k<Hsz; ++k) s += h[k]*w[k];
    out[b*PREDsz + p] = s + fb[p];
}

// ---------------- launch ----------------
extern "C" void kernel_launch(void* const* d_in, const int* in_sizes, int n_in,
                              void* d_out, int out_size)
{
    const float* x    = (const float*)d_in[0];
    const float* wih0 = (const float*)d_in[1];
    const float* whh0 = (const float*)d_in[2];
    const float* bih0 = (const float*)d_in[3];
    const float* bhh0 = (const float*)d_in[4];
    const float* wih1 = (const float*)d_in[5];
    const float* whh1 = (const float*)d_in[6];
    const float* bih1 = (const float*)d_in[7];
    const float* bhh1 = (const float*)d_in[8];
    const float* wih2 = (const float*)d_in[9];
    const float* whh2 = (const float*)d_in[10];
    const float* bih2 = (const float*)d_in[11];
    const float* bhh2 = (const float*)d_in[12];
    const float* fcw  = (const float*)d_in[13];
    const float* fcb  = (const float*)d_in[14];
    float* out = (float*)d_out;

    cudaFuncSetAttribute(k_scan, cudaFuncAttributeMaxDynamicSharedMemorySize, SCAN_SMEM_BYTES);

    dim3 gg(G3sz/128, MR/128);   // n fastest for L2 reuse

    // layer 0 (input x, permuted [B,T,IN] -> row t*B+b)
    k_gemm<<<gg, 256>>>(x, 0, wih0, bih0, INsz, 1);
    k_scan<<<NCTA, 512, SCAN_SMEM_BYTES>>>(whh0, bhh0, 1);
    // layer 1
    k_gemm<<<gg, 256>>>(nullptr, 1, wih1, bih1, Hsz, 0);
    k_scan<<<NCTA, 512, SCAN_SMEM_BYTES>>>(whh1, bhh1, 2);
    // layer 2
    k_gemm<<<gg, 256>>>(nullptr, 2, wih2, bih2, Hsz, 0);
    k_scan<<<NCTA, 512, SCAN_SMEM_BYTES>>>(whh2, bhh2, 1);
    // head
    k_fc<<<PREDsz, Bsz>>>(fcw, fcb, out);
}